// round 4
// baseline (speedup 1.0000x reference)
#include <cuda_runtime.h>
#include <cstdint>
#include <cstddef>

// ---------------------------------------------------------------------------
// NonOverlappingConv1d as batched GEMM:
//   out[b,o,p] = (1/sqrt(128)) * sum_{kidx=0..255} W[o][kidx] * B_b[p][kidx]
//   W[o][kidx]   = weight flat (row-major, kidx = 2c+k)
//   B_b[p][kidx] = x[b, kidx>>1, 2p + (kidx&1)]
// tf32 mma.sync (m16n8k8), fragment-order SMEM staging.
// ---------------------------------------------------------------------------

namespace {
constexpr int kBatch  = 32;
constexpr int kCin    = 128;
constexpr int kDin    = 8192;
constexpr int kP      = 4096;
constexpr int kO      = 128;
constexpr int kK      = 256;    // 2 * kCin
constexpr int kTileP  = 128;
constexpr int kKC     = 64;     // kidx per chunk (32 c-rows)
constexpr int kNChunks = kK / kKC;   // 4
constexpr int kThreads = 256;

// A (weights) fragment-order SMEM: [mt(8)][kt(32)][lane(32)*4regs + pad]
constexpr int A_BLK  = 132;               // 128 floats + 4 pad (bank spread)
constexpr int A_KT   = kK / 8;            // 32
constexpr int A_MT   = kO / 16;           // 8
constexpr int A_SIZE = A_MT * A_KT * A_BLK;   // 33792 floats

// B (x) fragment-order SMEM per chunk: [kt8(8)][tn(16)][lane(32)*2regs + pad]
constexpr int B_BLK  = 68;                // 64 floats + 4 pad
constexpr int B_KT8  = kKC / 8;           // 8
constexpr int B_NT   = kTileP / 8;        // 16
constexpr int B_SIZE = B_KT8 * B_NT * B_BLK;  // 8704 floats

constexpr int SMEM_FLOATS = A_SIZE + 2 * B_SIZE;   // 51200
constexpr int SMEM_BYTES  = SMEM_FLOATS * 4;       // 204800 B
}  // namespace

__device__ __forceinline__ float to_tf32(float x) {
  uint32_t u;
  asm("cvt.rna.tf32.f32 %0, %1;" : "=r"(u) : "f"(x));
  return __uint_as_float(u);
}

__device__ __forceinline__ void mma_tf32(float d[4], const uint32_t a[4],
                                         const uint32_t b[2]) {
  asm volatile(
      "mma.sync.aligned.m16n8k8.row.col.f32.tf32.tf32.f32 "
      "{%0,%1,%2,%3}, {%4,%5,%6,%7}, {%8,%9}, {%0,%1,%2,%3};"
      : "+f"(d[0]), "+f"(d[1]), "+f"(d[2]), "+f"(d[3])
      : "r"(a[0]), "r"(a[1]), "r"(a[2]), "r"(a[3]), "r"(b[0]), "r"(b[1]));
}

__global__ __launch_bounds__(kThreads, 1)
void conv1d_tf32_kernel(const float* __restrict__ x,
                        const float* __restrict__ w,
                        float* __restrict__ out) {
  extern __shared__ float smem[];
  float* sA = smem;
  float* sB = smem + A_SIZE;

  const int tid = threadIdx.x;
  const int b   = blockIdx.y;
  const int p0  = blockIdx.x * kTileP;

  // ------------------------------------------------------------------
  // Stage A (full 128x256 weights) into fragment order, tf32-rounded.
  // A fragment slot for (o, kidx): mt=o>>4, kt=kidx>>3, r=o&15, c=kidx&7
  //   lane = (r&7)*4 + (c&3);  reg = (r>>3) + ((c>>2)<<1)
  // ------------------------------------------------------------------
  #pragma unroll
  for (int it = 0; it < (kO * kK / 4) / kThreads; ++it) {   // 32 iters
    int lin = it * kThreads + tid;
    int o = lin >> 6;            // 64 float4 per weight row
    int j = lin & 63;
    float4 w4 = *reinterpret_cast<const float4*>(w + o * kK + 4 * j);
    float v[4] = {to_tf32(w4.x), to_tf32(w4.y), to_tf32(w4.z), to_tf32(w4.w)};
    int mt = o >> 4, r = o & 15, kt = j >> 1;
    float* base = sA + (mt * A_KT + kt) * A_BLK;
    #pragma unroll
    for (int e = 0; e < 4; ++e) {
      int c  = (4 * j + e) & 7;
      int ln = (r & 7) * 4 + (c & 3);
      int rg = (r >> 3) + ((c >> 2) << 1);
      base[ln * 4 + rg] = v[e];
    }
  }

  // ------------------------------------------------------------------
  // B staging: each chunk = 32 c-rows of 256 contiguous x-floats.
  // A float4 x[b,c,2p+0..3] deinterleaves into 4 fragment slots.
  // ------------------------------------------------------------------
  float4 vals[8];

  auto load_b = [&](int ch) {
    const float* xb = x + (size_t)(b * kCin + ch * 32) * kDin + 2 * p0;
    #pragma unroll
    for (int q = 0; q < 8; ++q) {
      int lin = q * kThreads + tid;
      int cl = lin >> 6;
      int f  = lin & 63;
      vals[q] = *reinterpret_cast<const float4*>(xb + (size_t)cl * kDin + 4 * f);
    }
  };

  auto store_b = [&](int buf) {
    float* sb = sB + buf * B_SIZE;
    #pragma unroll
    for (int q = 0; q < 8; ++q) {
      int lin = q * kThreads + tid;
      int cl = lin >> 6;
      int f  = lin & 63;
      float v[4] = {to_tf32(vals[q].x), to_tf32(vals[q].y),
                    to_tf32(vals[q].z), to_tf32(vals[q].w)};
      #pragma unroll
      for (int e = 0; e < 4; ++e) {
        int pl = 2 * f + (e >> 1);       // local p in [0,128)
        int kl = 2 * cl + (e & 1);       // local kidx in [0,64)
        int tn = pl >> 3, kt8 = kl >> 3;
        int ln = (pl & 7) * 4 + (kl & 3);
        int rg = (kl & 7) >> 2;
        sb[(kt8 * B_NT + tn) * B_BLK + ln * 2 + rg] = v[e];
      }
    }
  };

  // ------------------------------------------------------------------
  // Warp tiling: 8 warps, each 64(o) x 32(p).
  // ------------------------------------------------------------------
  const int lane = tid & 31;
  const int wid  = tid >> 5;
  const int wm = (wid >> 2) * 64;   // 0 or 64
  const int wn = (wid & 3) * 32;    // 0..96

  float acc[4][4][4];
  #pragma unroll
  for (int i = 0; i < 4; ++i)
    #pragma unroll
    for (int j2 = 0; j2 < 4; ++j2)
      #pragma unroll
      for (int r2 = 0; r2 < 4; ++r2) acc[i][j2][r2] = 0.f;

  auto mma_chunk = [&](int ch) {
    const float* sb = sB + (ch & 1) * B_SIZE;
    #pragma unroll
    for (int kt8 = 0; kt8 < 8; ++kt8) {
      int kt = ch * 8 + kt8;
      uint32_t afr[4][4];
      #pragma unroll
      for (int mt2 = 0; mt2 < 4; ++mt2) {
        int mt = (wm >> 4) + mt2;
        uint4 av = *reinterpret_cast<const uint4*>(
            sA + (mt * A_KT + kt) * A_BLK + lane * 4);
        afr[mt2][0] = av.x; afr[mt2][1] = av.y;
        afr[mt2][2] = av.z; afr[mt2][3] = av.w;
      }
      uint32_t bfr[4][2];
      #pragma unroll
      for (int nt = 0; nt < 4; ++nt) {
        int tn = (wn >> 3) + nt;
        uint2 bv = *reinterpret_cast<const uint2*>(
            sb + (kt8 * B_NT + tn) * B_BLK + lane * 2);
        bfr[nt][0] = bv.x; bfr[nt][1] = bv.y;
      }
      #pragma unroll
      for (int mt2 = 0; mt2 < 4; ++mt2)
        #pragma unroll
        for (int nt = 0; nt < 4; ++nt)
          mma_tf32(acc[mt2][nt], afr[mt2], bfr[nt]);
    }
  };

  // ------------------------------------------------------------------
  // Mainloop: double-buffered K-chunks, LDG prefetch under MMA.
  // ------------------------------------------------------------------
  load_b(0);
  store_b(0);
  __syncthreads();

  for (int ch = 0; ch < kNChunks; ++ch) {
    if (ch + 1 < kNChunks) load_b(ch + 1);
    mma_chunk(ch);
    if (ch + 1 < kNChunks) store_b((ch + 1) & 1);
    __syncthreads();
  }

  // ------------------------------------------------------------------
  // Epilogue: scale by 1/sqrt(128), float2 stores.
  // D frag: r0:(gid, 2tq) r1:(gid, 2tq+1) r2:(gid+8, 2tq) r3:(gid+8, 2tq+1)
  // ------------------------------------------------------------------
  const float scale = 0.08838834764831845f;   // 1/sqrt(128)
  const int gid = lane >> 2, tq = lane & 3;
  float* ob = out + (size_t)b * kO * kP;
  #pragma unroll
  for (int mt2 = 0; mt2 < 4; ++mt2) {
    int o_base = wm + mt2 * 16 + gid;
    #pragma unroll
    for (int nt = 0; nt < 4; ++nt) {
      int p = p0 + wn + nt * 8 + 2 * tq;
      float2 v0 = make_float2(acc[mt2][nt][0] * scale, acc[mt2][nt][1] * scale);
      float2 v1 = make_float2(acc[mt2][nt][2] * scale, acc[mt2][nt][3] * scale);
      *reinterpret_cast<float2*>(ob + (size_t)o_base * kP + p) = v0;
      *reinterpret_cast<float2*>(ob + (size_t)(o_base + 8) * kP + p) = v1;
    }
  }
}

extern "C" void kernel_launch(void* const* d_in, const int* in_sizes, int n_in,
                              void* d_out, int out_size) {
  const float* x = (const float*)d_in[0];
  const float* w = (const float*)d_in[1];
  // Defensive: identify operands by size (x: 33554432, weight: 32768).
  if (n_in >= 2 && in_sizes[0] == kO * kK) {
    const float* t = x; x = w; w = t;
  }
  (void)out_size;

  cudaFuncSetAttribute(conv1d_tf32_kernel,
                       cudaFuncAttributeMaxDynamicSharedMemorySize, SMEM_BYTES);

  dim3 grid(kP / kTileP, kBatch);   // (32, 32)
  conv1d_tf32_kernel<<<grid, kThreads, SMEM_BYTES>>>(x, w, (float*)d_out);
}